// round 3
// baseline (speedup 1.0000x reference)
#include <cuda_runtime.h>
#include <cuda_bf16.h>
#include <cstdint>

// Problem constants
#define BB 2
#define PP 64
#define NN 256
#define CC 512
#define HH 8
#define DD 64
#define BP (BB*PP)        // 128
#define MROWS (BP*NN)     // 32768
#define INV_TEMP 0.125f
#define LN_EPS 1e-5f

// ---------------- scratch (static device globals; allocation-free) ----------------
__device__ float g_qh[(size_t)MROWS * CC];
__device__ float g_kh[(size_t)MROWS * CC];
__device__ float g_vh[(size_t)MROWS * CC];
__device__ float g_ao[(size_t)MROWS * CC];
__device__ float g_mu[3 * MROWS];
__device__ float g_rs[3 * MROWS];

// ---------------- kernel 1: per-row LN stats for q,k,v ----------------
__global__ __launch_bounds__(256) void ln_stats_kernel(
    const float* __restrict__ q, const float* __restrict__ k, const float* __restrict__ v)
{
    int row = blockIdx.x * 8 + (threadIdx.x >> 5);   // 3*MROWS rows total
    int lane = threadIdx.x & 31;
    int t = row / MROWS;
    int r = row - t * MROWS;
    const float* x = (t == 0 ? q : (t == 1 ? k : v)) + (size_t)r * CC;
    float s = 0.f, ss = 0.f;
#pragma unroll
    for (int i = 0; i < 4; i++) {
        float4 u = reinterpret_cast<const float4*>(x)[lane + 32 * i];
        s  += u.x + u.y + u.z + u.w;
        ss += u.x*u.x + u.y*u.y + u.z*u.z + u.w*u.w;
    }
#pragma unroll
    for (int o = 16; o; o >>= 1) {
        s  += __shfl_xor_sync(0xffffffffu, s, o);
        ss += __shfl_xor_sync(0xffffffffu, ss, o);
    }
    if (lane == 0) {
        float mu = s * (1.f / CC);
        float var = ss * (1.f / CC) - mu * mu;
        g_mu[row] = mu;
        g_rs[row] = rsqrtf(var + LN_EPS);
    }
}

// ---------------- kernel 2: fused-LN projection GEMM  Y = LN(X) @ W^T ----------------
// BM=128 BN=128 BK=16, 256 threads, 8x8 per-thread
__global__ __launch_bounds__(256, 2) void proj_gemm_kernel(
    const float* __restrict__ q, const float* __restrict__ k, const float* __restrict__ v,
    const float* __restrict__ Wq, const float* __restrict__ Wk, const float* __restrict__ Wv,
    const float* __restrict__ gq, const float* __restrict__ bq,
    const float* __restrict__ gk, const float* __restrict__ bk,
    const float* __restrict__ gv, const float* __restrict__ bv)
{
    int t = blockIdx.z;
    const float* X = (t == 0 ? q : (t == 1 ? k : v));
    const float* W = (t == 0 ? Wq : (t == 1 ? Wk : Wv));
    const float* G = (t == 0 ? gq : (t == 1 ? gk : gv));
    const float* Bv = (t == 0 ? bq : (t == 1 ? bk : bv));
    float* Y = (t == 0 ? g_qh : (t == 1 ? g_kh : g_vh));
    const float* mu = g_mu + t * MROWS;
    const float* rs = g_rs + t * MROWS;

    __shared__ float As[16][132];
    __shared__ float Bs[16][132];

    const int m0 = blockIdx.y * 128;
    const int n0 = blockIdx.x * 128;
    const int tid = threadIdx.x;
    const int ar  = tid >> 2;          // 0..63
    const int ac4 = (tid & 3) * 4;     // 0,4,8,12
    const int tx = tid & 15, ty = tid >> 4;

    const float mu0 = mu[m0 + ar],      rs0 = rs[m0 + ar];
    const float mu1 = mu[m0 + ar + 64], rs1 = rs[m0 + ar + 64];

    float acc[8][8];
#pragma unroll
    for (int i = 0; i < 8; i++)
#pragma unroll
        for (int j = 0; j < 8; j++) acc[i][j] = 0.f;

    for (int k0 = 0; k0 < CC; k0 += 16) {
        float4 ga = *reinterpret_cast<const float4*>(G  + k0 + ac4);
        float4 ba = *reinterpret_cast<const float4*>(Bv + k0 + ac4);
        float4 a0 = *reinterpret_cast<const float4*>(X + (size_t)(m0 + ar)      * CC + k0 + ac4);
        float4 a1 = *reinterpret_cast<const float4*>(X + (size_t)(m0 + ar + 64) * CC + k0 + ac4);
        float4 b0 = *reinterpret_cast<const float4*>(W + (size_t)(n0 + ar)      * CC + k0 + ac4);
        float4 b1 = *reinterpret_cast<const float4*>(W + (size_t)(n0 + ar + 64) * CC + k0 + ac4);
        // apply LayerNorm to A
        a0.x = (a0.x - mu0) * rs0 * ga.x + ba.x;  a0.y = (a0.y - mu0) * rs0 * ga.y + ba.y;
        a0.z = (a0.z - mu0) * rs0 * ga.z + ba.z;  a0.w = (a0.w - mu0) * rs0 * ga.w + ba.w;
        a1.x = (a1.x - mu1) * rs1 * ga.x + ba.x;  a1.y = (a1.y - mu1) * rs1 * ga.y + ba.y;
        a1.z = (a1.z - mu1) * rs1 * ga.z + ba.z;  a1.w = (a1.w - mu1) * rs1 * ga.w + ba.w;

        __syncthreads();
        As[ac4 + 0][ar] = a0.x; As[ac4 + 1][ar] = a0.y; As[ac4 + 2][ar] = a0.z; As[ac4 + 3][ar] = a0.w;
        As[ac4 + 0][ar + 64] = a1.x; As[ac4 + 1][ar + 64] = a1.y; As[ac4 + 2][ar + 64] = a1.z; As[ac4 + 3][ar + 64] = a1.w;
        Bs[ac4 + 0][ar] = b0.x; Bs[ac4 + 1][ar] = b0.y; Bs[ac4 + 2][ar] = b0.z; Bs[ac4 + 3][ar] = b0.w;
        Bs[ac4 + 0][ar + 64] = b1.x; Bs[ac4 + 1][ar + 64] = b1.y; Bs[ac4 + 2][ar + 64] = b1.z; Bs[ac4 + 3][ar + 64] = b1.w;
        __syncthreads();

#pragma unroll
        for (int kk = 0; kk < 16; kk++) {
            float4 af0 = *reinterpret_cast<float4*>(&As[kk][ty * 8]);
            float4 af1 = *reinterpret_cast<float4*>(&As[kk][ty * 8 + 4]);
            float4 bf0 = *reinterpret_cast<float4*>(&Bs[kk][tx * 8]);
            float4 bf1 = *reinterpret_cast<float4*>(&Bs[kk][tx * 8 + 4]);
            float a_[8] = {af0.x, af0.y, af0.z, af0.w, af1.x, af1.y, af1.z, af1.w};
            float b_[8] = {bf0.x, bf0.y, bf0.z, bf0.w, bf1.x, bf1.y, bf1.z, bf1.w};
#pragma unroll
            for (int i = 0; i < 8; i++)
#pragma unroll
                for (int j = 0; j < 8; j++) acc[i][j] = fmaf(a_[i], b_[j], acc[i][j]);
        }
    }
#pragma unroll
    for (int i = 0; i < 8; i++) {
        float4 o0 = {acc[i][0], acc[i][1], acc[i][2], acc[i][3]};
        float4 o1 = {acc[i][4], acc[i][5], acc[i][6], acc[i][7]};
        size_t base = (size_t)(m0 + ty * 8 + i) * CC + n0 + tx * 8;
        *reinterpret_cast<float4*>(Y + base)     = o0;
        *reinterpret_cast<float4*>(Y + base + 4) = o1;
    }
}

// ---------------- kernel 3: windowed masked attention ----------------
// grid (H, BP); 256 threads = 8 warps; each warp owns 32 query rows.
#define KS_STRIDE 68
#define SMEM_ATTN ((2 * 256 * KS_STRIDE + 64 * KS_STRIDE + 8 * 8 * 256) * 4)

__global__ __launch_bounds__(256, 1) void attn_kernel(
    const float* __restrict__ mask, const float* __restrict__ pos)
{
    extern __shared__ float sm[];
    float* Ks = sm;                              // 256 x 68
    float* Vs = Ks + 256 * KS_STRIDE;            // 256 x 68
    float* qs = Vs + 256 * KS_STRIDE;            // 8 warps x 8 rows x 68
    float* pb = qs + 64 * KS_STRIDE;             // 8 warps x 8 rows x 256

    const int h  = blockIdx.x;
    const int bp = blockIdx.y;
    const int tid = threadIdx.x;
    const int w = tid >> 5, lane = tid & 31;

    // load K,V head tiles into shared (stride-68 padded)
    for (int idx = tid; idx < 256 * 16; idx += 256) {
        int j = idx >> 4, c4 = (idx & 15) * 4;
        size_t g = (size_t)(bp * NN + j) * CC + h * DD + c4;
        *reinterpret_cast<float4*>(&Ks[j * KS_STRIDE + c4]) = *reinterpret_cast<const float4*>(g_kh + g);
        *reinterpret_cast<float4*>(&Vs[j * KS_STRIDE + c4]) = *reinterpret_cast<const float4*>(g_vh + g);
    }
    __syncthreads();

    const float* mbase = mask + (size_t)bp * NN * NN;
    const float* pbase = pos  + (size_t)h  * NN * NN;

    for (int g = 0; g < 4; g++) {
        const int r0 = w * 32 + g * 8;
        // stage this warp's 8 query rows
        __syncwarp();
#pragma unroll
        for (int ii = 0; ii < 4; ii++) {
            int idx = lane + 32 * ii;            // 0..127
            int r = idx >> 4, c4 = (idx & 15) * 4;
            float4 u = *reinterpret_cast<const float4*>(
                g_qh + (size_t)(bp * NN + r0 + r) * CC + h * DD + c4);
            *reinterpret_cast<float4*>(&qs[(w * 8 + r) * KS_STRIDE + c4]) = u;
        }
        __syncwarp();

        // S = q @ K^T : lane owns j = lane + 32t, 8 rows x 8 j
        float s[8][8];
#pragma unroll
        for (int r = 0; r < 8; r++)
#pragma unroll
            for (int t = 0; t < 8; t++) s[r][t] = 0.f;

#pragma unroll
        for (int c4 = 0; c4 < DD; c4 += 4) {
            float4 kf[8];
#pragma unroll
            for (int t = 0; t < 8; t++)
                kf[t] = *reinterpret_cast<const float4*>(&Ks[(lane + 32 * t) * KS_STRIDE + c4]);
#pragma unroll
            for (int r = 0; r < 8; r++) {
                float4 qf = *reinterpret_cast<const float4*>(&qs[(w * 8 + r) * KS_STRIDE + c4]);
#pragma unroll
                for (int t = 0; t < 8; t++) {
                    s[r][t] = fmaf(qf.x, kf[t].x, s[r][t]);
                    s[r][t] = fmaf(qf.y, kf[t].y, s[r][t]);
                    s[r][t] = fmaf(qf.z, kf[t].z, s[r][t]);
                    s[r][t] = fmaf(qf.w, kf[t].w, s[r][t]);
                }
            }
        }

        // softmax(mask * (s*invtemp + pos)) per row, write p to shared
#pragma unroll
        for (int r = 0; r < 8; r++) {
            int i = r0 + r;
            const float* mrow = mbase + (size_t)i * NN;
            const float* prow = pbase + (size_t)i * NN;
            float sv[8];
            float mx = -1e30f;
#pragma unroll
            for (int t = 0; t < 8; t++) {
                int j = lane + 32 * t;
                float x = __ldg(mrow + j) * (s[r][t] * INV_TEMP + __ldg(prow + j));
                sv[t] = x;
                mx = fmaxf(mx, x);
            }
#pragma unroll
            for (int o = 16; o; o >>= 1) mx = fmaxf(mx, __shfl_xor_sync(0xffffffffu, mx, o));
            float se = 0.f;
#pragma unroll
            for (int t = 0; t < 8; t++) { float e = __expf(sv[t] - mx); sv[t] = e; se += e; }
#pragma unroll
            for (int o = 16; o; o >>= 1) se += __shfl_xor_sync(0xffffffffu, se, o);
            float inv = 1.f / se;
#pragma unroll
            for (int t = 0; t < 8; t++) pb[(w * 8 + r) * NN + lane + 32 * t] = sv[t] * inv;
        }
        __syncwarp();

        // out = P @ V : lane owns d = {2*lane, 2*lane+1}
        float o0[8], o1[8];
#pragma unroll
        for (int r = 0; r < 8; r++) { o0[r] = 0.f; o1[r] = 0.f; }
#pragma unroll 4
        for (int j = 0; j < NN; j++) {
            float2 vv = *reinterpret_cast<const float2*>(&Vs[j * KS_STRIDE + 2 * lane]);
#pragma unroll
            for (int r = 0; r < 8; r++) {
                float pj = pb[(w * 8 + r) * NN + j];
                o0[r] = fmaf(pj, vv.x, o0[r]);
                o1[r] = fmaf(pj, vv.y, o1[r]);
            }
        }
#pragma unroll
        for (int r = 0; r < 8; r++) {
            float2 ov = {o0[r], o1[r]};
            *reinterpret_cast<float2*>(
                g_ao + (size_t)(bp * NN + r0 + r) * CC + h * DD + 2 * lane) = ov;
        }
        __syncwarp();
    }
}

// ---------------- kernel 4: output GEMM  out = AO @ Wo^T + bo ----------------
__global__ __launch_bounds__(256, 2) void out_gemm_kernel(
    const float* __restrict__ Wo, const float* __restrict__ bo, float* __restrict__ Y)
{
    __shared__ float As[16][132];
    __shared__ float Bs[16][132];

    const int m0 = blockIdx.y * 128;
    const int n0 = blockIdx.x * 128;
    const int tid = threadIdx.x;
    const int ar  = tid >> 2;
    const int ac4 = (tid & 3) * 4;
    const int tx = tid & 15, ty = tid >> 4;

    float acc[8][8];
#pragma unroll
    for (int i = 0; i < 8; i++)
#pragma unroll
        for (int j = 0; j < 8; j++) acc[i][j] = 0.f;

    for (int k0 = 0; k0 < CC; k0 += 16) {
        float4 a0 = *reinterpret_cast<const float4*>(g_ao + (size_t)(m0 + ar)      * CC + k0 + ac4);
        float4 a1 = *reinterpret_cast<const float4*>(g_ao + (size_t)(m0 + ar + 64) * CC + k0 + ac4);
        float4 b0 = *reinterpret_cast<const float4*>(Wo   + (size_t)(n0 + ar)      * CC + k0 + ac4);
        float4 b1 = *reinterpret_cast<const float4*>(Wo   + (size_t)(n0 + ar + 64) * CC + k0 + ac4);

        __syncthreads();
        As[ac4 + 0][ar] = a0.x; As[ac4 + 1][ar] = a0.y; As[ac4 + 2][ar] = a0.z; As[ac4 + 3][ar] = a0.w;
        As[ac4 + 0][ar + 64] = a1.x; As[ac4 + 1][ar + 64] = a1.y; As[ac4 + 2][ar + 64] = a1.z; As[ac4 + 3][ar + 64] = a1.w;
        Bs[ac4 + 0][ar] = b0.x; Bs[ac4 + 1][ar] = b0.y; Bs[ac4 + 2][ar] = b0.z; Bs[ac4 + 3][ar] = b0.w;
        Bs[ac4 + 0][ar + 64] = b1.x; Bs[ac4 + 1][ar + 64] = b1.y; Bs[ac4 + 2][ar + 64] = b1.z; Bs[ac4 + 3][ar + 64] = b1.w;
        __syncthreads();

#pragma unroll
        for (int kk = 0; kk < 16; kk++) {
            float4 af0 = *reinterpret_cast<float4*>(&As[kk][ty * 8]);
            float4 af1 = *reinterpret_cast<float4*>(&As[kk][ty * 8 + 4]);
            float4 bf0 = *reinterpret_cast<float4*>(&Bs[kk][tx * 8]);
            float4 bf1 = *reinterpret_cast<float4*>(&Bs[kk][tx * 8 + 4]);
            float a_[8] = {af0.x, af0.y, af0.z, af0.w, af1.x, af1.y, af1.z, af1.w};
            float b_[8] = {bf0.x, bf0.y, bf0.z, bf0.w, bf1.x, bf1.y, bf1.z, bf1.w};
#pragma unroll
            for (int i = 0; i < 8; i++)
#pragma unroll
                for (int j = 0; j < 8; j++) acc[i][j] = fmaf(a_[i], b_[j], acc[i][j]);
        }
    }
#pragma unroll
    for (int i = 0; i < 8; i++) {
        int nn = n0 + tx * 8;
        float4 o0 = {acc[i][0] + bo[nn + 0], acc[i][1] + bo[nn + 1],
                     acc[i][2] + bo[nn + 2], acc[i][3] + bo[nn + 3]};
        float4 o1 = {acc[i][4] + bo[nn + 4], acc[i][5] + bo[nn + 5],
                     acc[i][6] + bo[nn + 6], acc[i][7] + bo[nn + 7]};
        size_t base = (size_t)(m0 + ty * 8 + i) * CC + nn;
        *reinterpret_cast<float4*>(Y + base)     = o0;
        *reinterpret_cast<float4*>(Y + base + 4) = o1;
    }
}

// ---------------- launch ----------------
extern "C" void kernel_launch(void* const* d_in, const int* in_sizes, int n_in,
                              void* d_out, int out_size)
{
    const float* q    = (const float*)d_in[0];
    const float* k    = (const float*)d_in[1];
    const float* v    = (const float*)d_in[2];
    const float* mask = (const float*)d_in[3];
    const float* pos  = (const float*)d_in[4];
    const float* gq   = (const float*)d_in[5];
    const float* bq   = (const float*)d_in[6];
    const float* gk   = (const float*)d_in[7];
    const float* bk   = (const float*)d_in[8];
    const float* gv   = (const float*)d_in[9];
    const float* bv   = (const float*)d_in[10];
    const float* Wq   = (const float*)d_in[11];
    const float* Wk   = (const float*)d_in[12];
    const float* Wv   = (const float*)d_in[13];
    const float* Wo   = (const float*)d_in[14];
    const float* bo   = (const float*)d_in[15];
    float* out = (float*)d_out;

    static bool attr_done = false;
    if (!attr_done) {
        cudaFuncSetAttribute(attn_kernel, cudaFuncAttributeMaxDynamicSharedMemorySize, SMEM_ATTN);
        attr_done = true;
    }

    ln_stats_kernel<<<(3 * MROWS) / 8, 256>>>(q, k, v);

    dim3 gp(CC / 128, MROWS / 128, 3);
    proj_gemm_kernel<<<gp, 256>>>(q, k, v, Wq, Wk, Wv, gq, bq, gk, bk, gv, bv);

    attn_kernel<<<dim3(HH, BP), 256, SMEM_ATTN>>>(mask, pos);

    dim3 go(CC / 128, MROWS / 128);
    out_gemm_kernel<<<go, 256>>>(Wo, bo, out);
}

// round 5
// speedup vs baseline: 1.6835x; 1.6835x over previous
#include <cuda_runtime.h>
#include <cuda_bf16.h>
#include <cstdint>

// Problem constants
#define BB 2
#define PP 64
#define NN 256
#define CC 512
#define HH 8
#define DD 64
#define BP (BB*PP)        // 128
#define MROWS (BP*NN)     // 32768
#define INV_TEMP 0.125f
#define LN_EPS 1e-5f

// ---------------- scratch (static device globals; allocation-free) ----------------
__device__ float g_qh[(size_t)MROWS * CC];
__device__ float g_kh[(size_t)MROWS * CC];
__device__ float g_vh[(size_t)MROWS * CC];
__device__ float g_ao[(size_t)MROWS * CC];

// bf16 split operands
__device__ __nv_bfloat16 g_ah[3][(size_t)MROWS * CC];   // LN(q/k/v) hi
__device__ __nv_bfloat16 g_al[3][(size_t)MROWS * CC];   // LN(q/k/v) lo
__device__ __nv_bfloat16 g_aoh[(size_t)MROWS * CC];     // attn out hi
__device__ __nv_bfloat16 g_aol[(size_t)MROWS * CC];     // attn out lo
__device__ __nv_bfloat16 g_wh[4][(size_t)CC * CC];      // Wq,Wk,Wv,Wo hi
__device__ __nv_bfloat16 g_wl[4][(size_t)CC * CC];      // Wq,Wk,Wv,Wo lo

// ---------------- helpers ----------------
__device__ __forceinline__ uint32_t s2u(const void* p) {
    uint32_t a;
    asm("{ .reg .u64 t; cvta.to.shared.u64 t, %1; cvt.u32.u64 %0, t; }" : "=r"(a) : "l"(p));
    return a;
}

__device__ __forceinline__ void cp16(uint32_t dst, const void* src) {
    asm volatile("cp.async.cg.shared.global [%0], [%1], 16;" :: "r"(dst), "l"(src) : "memory");
}

__device__ __forceinline__ void ldm4(uint32_t* r, uint32_t addr) {
    asm volatile("ldmatrix.sync.aligned.m8n8.x4.shared.b16 {%0,%1,%2,%3}, [%4];"
                 : "=r"(r[0]), "=r"(r[1]), "=r"(r[2]), "=r"(r[3]) : "r"(addr));
}

__device__ __forceinline__ void mma16816(float* c, const uint32_t* a, const uint32_t* b) {
    asm volatile(
        "mma.sync.aligned.m16n8k16.row.col.f32.bf16.bf16.f32 "
        "{%0,%1,%2,%3}, {%4,%5,%6,%7}, {%8,%9}, {%0,%1,%2,%3};"
        : "+f"(c[0]), "+f"(c[1]), "+f"(c[2]), "+f"(c[3])
        : "r"(a[0]), "r"(a[1]), "r"(a[2]), "r"(a[3]), "r"(b[0]), "r"(b[1]));
}

__device__ __forceinline__ void split2(float y, __nv_bfloat16& h, __nv_bfloat16& l) {
    h = __float2bfloat16(y);
    l = __float2bfloat16(y - __bfloat162float(h));
}

// ---------------- kernel 1: fused LayerNorm + bf16 hi/lo split for q,k,v ----------------
__global__ __launch_bounds__(128) void split_ln_kernel(
    const float* __restrict__ q, const float* __restrict__ k, const float* __restrict__ v,
    const float* __restrict__ gq, const float* __restrict__ bq,
    const float* __restrict__ gk, const float* __restrict__ bk,
    const float* __restrict__ gv, const float* __restrict__ bv)
{
    int row = blockIdx.x;                       // 0 .. 3*MROWS-1
    int t = (row >= 2 * MROWS) ? 2 : (row >= MROWS ? 1 : 0);
    int r = row - t * MROWS;
    const float* X = (t == 0 ? q : (t == 1 ? k : v)) + (size_t)r * CC;
    const float* G = (t == 0 ? gq : (t == 1 ? gk : gv));
    const float* Bb = (t == 0 ? bq : (t == 1 ? bk : bv));
    __nv_bfloat16* H = g_ah[t] + (size_t)r * CC;
    __nv_bfloat16* L = g_al[t] + (size_t)r * CC;

    int tid = threadIdx.x, lane = tid & 31, wid = tid >> 5;
    float4 u = reinterpret_cast<const float4*>(X)[tid];
    float s = u.x + u.y + u.z + u.w;
    float ss = u.x * u.x + u.y * u.y + u.z * u.z + u.w * u.w;
#pragma unroll
    for (int o = 16; o; o >>= 1) {
        s  += __shfl_xor_sync(0xffffffffu, s, o);
        ss += __shfl_xor_sync(0xffffffffu, ss, o);
    }
    __shared__ float sm1[4], sm2[4];
    if (lane == 0) { sm1[wid] = s; sm2[wid] = ss; }
    __syncthreads();
    s  = sm1[0] + sm1[1] + sm1[2] + sm1[3];
    ss = sm2[0] + sm2[1] + sm2[2] + sm2[3];
    float mu = s * (1.f / CC);
    float rs = rsqrtf(ss * (1.f / CC) - mu * mu + LN_EPS);

    float4 g4 = reinterpret_cast<const float4*>(G)[tid];
    float4 b4 = reinterpret_cast<const float4*>(Bb)[tid];
    float y0 = (u.x - mu) * rs * g4.x + b4.x;
    float y1 = (u.y - mu) * rs * g4.y + b4.y;
    float y2 = (u.z - mu) * rs * g4.z + b4.z;
    float y3 = (u.w - mu) * rs * g4.w + b4.w;

    __nv_bfloat16 h0, h1, h2, h3, l0, l1, l2, l3;
    split2(y0, h0, l0); split2(y1, h1, l1); split2(y2, h2, l2); split2(y3, h3, l3);
    __nv_bfloat162 hp0; hp0.x = h0; hp0.y = h1;
    __nv_bfloat162 hp1; hp1.x = h2; hp1.y = h3;
    __nv_bfloat162 lp0; lp0.x = l0; lp0.y = l1;
    __nv_bfloat162 lp1; lp1.x = l2; lp1.y = l3;
    reinterpret_cast<__nv_bfloat162*>(H)[2 * tid]     = hp0;
    reinterpret_cast<__nv_bfloat162*>(H)[2 * tid + 1] = hp1;
    reinterpret_cast<__nv_bfloat162*>(L)[2 * tid]     = lp0;
    reinterpret_cast<__nv_bfloat162*>(L)[2 * tid + 1] = lp1;
}

// ---------------- kernel 2: generic fp32 -> bf16 hi/lo split ----------------
__global__ __launch_bounds__(256) void split_kernel(const float* __restrict__ src, int mode, int n4)
{
    __nv_bfloat16 *H, *L;
    const float* S = src;
    if (mode < 4) { H = g_wh[mode]; L = g_wl[mode]; }
    else          { H = g_aoh; L = g_aol; S = g_ao; }
    int i = blockIdx.x * 256 + threadIdx.x;
    if (i >= n4) return;
    float4 u = reinterpret_cast<const float4*>(S)[i];
    __nv_bfloat16 h0, h1, h2, h3, l0, l1, l2, l3;
    split2(u.x, h0, l0); split2(u.y, h1, l1); split2(u.z, h2, l2); split2(u.w, h3, l3);
    __nv_bfloat162 hp0; hp0.x = h0; hp0.y = h1;
    __nv_bfloat162 hp1; hp1.x = h2; hp1.y = h3;
    __nv_bfloat162 lp0; lp0.x = l0; lp0.y = l1;
    __nv_bfloat162 lp1; lp1.x = l2; lp1.y = l3;
    reinterpret_cast<__nv_bfloat162*>(H)[2 * i]     = hp0;
    reinterpret_cast<__nv_bfloat162*>(H)[2 * i + 1] = hp1;
    reinterpret_cast<__nv_bfloat162*>(L)[2 * i]     = lp0;
    reinterpret_cast<__nv_bfloat162*>(L)[2 * i + 1] = lp1;
}

// ---------------- kernel 3: HMMA bf16 GEMM, Y[m][n] = sum_k A[m][k]*W[n][k] (+bias) ----------------
// 3-term split: Ah*Bh + Ah*Bl + Al*Bh, fp32 accumulate.
// CTA 128x128, BK=32; smem tiles 128x32 bf16 (row=64B, 4 chunks of 16B,
// swizzle: chunk ^= (row>>1)&3), double-buffered cp.async.
#define TILE_B 8192
#define STAGE_B 32768
#define GSMEM (2 * STAGE_B)
#define NKI (CC / 32)

__global__ __launch_bounds__(256, 2)
void mma_gemm_kernel(int base_mode, float* __restrict__ out_param, const float* __restrict__ bias_param)
{
    extern __shared__ char smc[];
    const uint32_t sb = s2u(smc);
    const int tid = threadIdx.x, wid = tid >> 5, lane = tid & 31;
    const int warp_m = wid >> 2, warp_n = wid & 3;       // 2 x 4 warps
    const int m0 = blockIdx.y * 128, n0 = blockIdx.x * 128;
    const int mode = base_mode + blockIdx.z;

    const __nv_bfloat16 *Ah, *Al;
    float* O;
    const float* bias = nullptr;
    if (mode < 3) {
        Ah = g_ah[mode]; Al = g_al[mode];
        O = (mode == 0 ? g_qh : (mode == 1 ? g_kh : g_vh));
    } else {
        Ah = g_aoh; Al = g_aol; O = out_param; bias = bias_param;
    }
    const __nv_bfloat16* Bh = g_wh[mode];
    const __nv_bfloat16* Bl = g_wl[mode];

    float acc[4][4][4];
#pragma unroll
    for (int i = 0; i < 4; i++)
#pragma unroll
        for (int j = 0; j < 4; j++)
#pragma unroll
            for (int x = 0; x < 4; x++) acc[i][j][x] = 0.f;

    const int lrow = tid >> 1;          // 0..127
    const int lc0  = (tid & 1) * 2;     // chunk 0 or 2

    // ---- loader: one BK=32 slab of all 4 tiles into stage s ----
    auto issue_loads = [&](int s, int k0) {
        uint32_t sst = sb + s * STAGE_B;
        const size_t ga = (size_t)(m0 + lrow) * CC + k0;
        const size_t gb = (size_t)(n0 + lrow) * CC + k0;
#pragma unroll
        for (int i = 0; i < 2; i++) {
            int c = lc0 + i;
            uint32_t d = (uint32_t)(lrow * 64 + ((c ^ ((lrow >> 1) & 3)) * 16));
            cp16(sst + 0 * TILE_B + d, Ah + ga + c * 8);
            cp16(sst + 1 * TILE_B + d, Al + ga + c * 8);
            cp16(sst + 2 * TILE_B + d, Bh + gb + c * 8);
            cp16(sst + 3 * TILE_B + d, Bl + gb + c * 8);
        }
    };

    issue_loads(0, 0);
    asm volatile("cp.async.commit_group;" ::: "memory");

    for (int it = 0; it < NKI; it++) {
        if (it + 1 < NKI) {
            issue_loads((it + 1) & 1, (it + 1) * 32);
            asm volatile("cp.async.commit_group;" ::: "memory");
            asm volatile("cp.async.wait_group 1;" ::: "memory");
        } else {
            asm volatile("cp.async.wait_group 0;" ::: "memory");
        }
        __syncthreads();

        const uint32_t st = sb + (it & 1) * STAGE_B;
#pragma unroll
        for (int kk = 0; kk < 2; kk++) {
            // fragment smem addresses (swizzled)
            uint32_t af[4][4], bf[2][4];
            // A address: row = warp_m*64 + mt*16 + (lane&7) + ((lane>>3)&1)*8 ; chunk = kk*2 + (lane>>4)
            // B address: row = warp_n*32 + np*16 + (lane&7) + ((lane>>4)&1)*8 ; chunk = kk*2 + ((lane>>3)&1)
            int ar = warp_m * 64 + (lane & 7) + ((lane >> 3) & 1) * 8;
            int ac = kk * 2 + ((lane >> 4) & 1);
            int br = warp_n * 32 + (lane & 7) + ((lane >> 4) & 1) * 8;
            int bc = kk * 2 + ((lane >> 3) & 1);

            // Bh + Ah
#pragma unroll
            for (int np = 0; np < 2; np++) {
                int r = br + np * 16;
                ldm4(bf[np], st + 2 * TILE_B + r * 64 + ((bc ^ ((r >> 1) & 3)) * 16));
            }
#pragma unroll
            for (int mt = 0; mt < 4; mt++) {
                int r = ar + mt * 16;
                ldm4(af[mt], st + 0 * TILE_B + r * 64 + ((ac ^ ((r >> 1) & 3)) * 16));
            }
#pragma unroll
            for (int mt = 0; mt < 4; mt++)
#pragma unroll
                for (int nt = 0; nt < 4; nt++)
                    mma16816(acc[mt][nt], af[mt], &bf[nt >> 1][(nt & 1) * 2]);

            // Bl (overwrite bf): Ah * Bl
#pragma unroll
            for (int np = 0; np < 2; np++) {
                int r = br + np * 16;
                ldm4(bf[np], st + 3 * TILE_B + r * 64 + ((bc ^ ((r >> 1) & 3)) * 16));
            }
#pragma unroll
            for (int mt = 0; mt < 4; mt++)
#pragma unroll
                for (int nt = 0; nt < 4; nt++)
                    mma16816(acc[mt][nt], af[mt], &bf[nt >> 1][(nt & 1) * 2]);

            // Al (overwrite af), Bh (overwrite bf): Al * Bh
#pragma unroll
            for (int mt = 0; mt < 4; mt++) {
                int r = ar + mt * 16;
                ldm4(af[mt], st + 1 * TILE_B + r * 64 + ((ac ^ ((r >> 1) & 3)) * 16));
            }
#pragma unroll
            for (int np = 0; np < 2; np++) {
                int r = br + np * 16;
                ldm4(bf[np], st + 2 * TILE_B + r * 64 + ((bc ^ ((r >> 1) & 3)) * 16));
            }
#pragma unroll
            for (int mt = 0; mt < 4; mt++)
#pragma unroll
                for (int nt = 0; nt < 4; nt++)
                    mma16816(acc[mt][nt], af[mt], &bf[nt >> 1][(nt & 1) * 2]);
        }
        __syncthreads();
    }

    // epilogue
#pragma unroll
    for (int mt = 0; mt < 4; mt++) {
#pragma unroll
        for (int nt = 0; nt < 4; nt++) {
            int r = m0 + warp_m * 64 + mt * 16 + (lane >> 2);
            int col = n0 + warp_n * 32 + nt * 8 + (lane & 3) * 2;
            float2 v0 = {acc[mt][nt][0], acc[mt][nt][1]};
            float2 v1 = {acc[mt][nt][2], acc[mt][nt][3]};
            if (bias) {
                float b0 = bias[col], b1 = bias[col + 1];
                v0.x += b0; v0.y += b1; v1.x += b0; v1.y += b1;
            }
            *reinterpret_cast<float2*>(O + (size_t)r * CC + col) = v0;
            *reinterpret_cast<float2*>(O + (size_t)(r + 8) * CC + col) = v1;
        }
    }
}

// ---------------- kernel 4: windowed masked attention (fp32 SIMT) ----------------
#define KS_STRIDE 68
#define SMEM_ATTN ((2 * 256 * KS_STRIDE + 64 * KS_STRIDE + 8 * 8 * 256) * 4)

__global__ __launch_bounds__(256, 1) void attn_kernel(
    const float* __restrict__ mask, const float* __restrict__ pos)
{
    extern __shared__ float smf[];
    float* Ks = smf;                             // 256 x 68
    float* Vs = Ks + 256 * KS_STRIDE;            // 256 x 68
    float* qs = Vs + 256 * KS_STRIDE;            // 8 warps x 8 rows x 68
    float* pb = qs + 64 * KS_STRIDE;             // 8 warps x 8 rows x 256

    const int h  = blockIdx.x;
    const int bp = blockIdx.y;
    const int tid = threadIdx.x;
    const int w = tid >> 5, lane = tid & 31;

    for (int idx = tid; idx < 256 * 16; idx += 256) {
        int j = idx >> 4, c4 = (idx & 15) * 4;
        size_t g = (size_t)(bp * NN + j) * CC + h * DD + c4;
        *reinterpret_cast<float4*>(&Ks[j * KS_STRIDE + c4]) = *reinterpret_cast<const float4*>(g_kh + g);
        *reinterpret_cast<float4*>(&Vs[j * KS_STRIDE + c4]) = *reinterpret_cast<const float4*>(g_vh + g);
    }
    __syncthreads();

    const float* mbase = mask + (size_t)bp * NN * NN;
    const float* pbase = pos  + (size_t)h  * NN * NN;

    for (int g = 0; g < 4; g++) {
        const int r0 = w * 32 + g * 8;
        __syncwarp();
#pragma unroll
        for (int ii = 0; ii < 4; ii++) {
            int idx = lane + 32 * ii;
            int r = idx >> 4, c4 = (idx & 15) * 4;
            float4 u = *reinterpret_cast<const float4*>(
                g_qh + (size_t)(bp * NN + r0 + r) * CC + h * DD + c4);
            *reinterpret_cast<float4*>(&qs[(w * 8 + r) * KS_STRIDE + c4]) = u;
        }
        __syncwarp();

        float s[8][8];
#pragma unroll
        for (int r = 0; r < 8; r++)
#pragma unroll
            for (int t = 0; t < 8; t++) s[r][t] = 0.f;

#pragma unroll
        for (int c4 = 0; c4 < DD; c4 += 4) {
            float4 kf[8];
#pragma unroll
            for (int t = 0; t < 8; t++)
                kf[t] = *reinterpret_cast<const float4*>(&Ks[(lane + 32 * t) * KS_STRIDE + c4]);
#pragma unroll
            for (int r = 0; r < 8; r++) {
                float4 qf = *reinterpret_cast<const float4*>(&qs[(w * 8 + r) * KS_STRIDE + c4]);
#pragma unroll
                for (int t = 0; t < 8; t++) {
                    s[r][t] = fmaf(qf.x, kf[t].x, s[r][t]);
                    s[r][t] = fmaf(qf.y, kf[t].y, s[r][t]);
                    s[r][t] = fmaf(qf.z, kf[t].z, s[r][t]);
                    s[r][t] = fmaf(qf.w, kf[t].w, s[r][t]);
                }
            }
        }

#pragma unroll
        for (int r = 0; r < 8; r++) {
            int i = r0 + r;
            const float* mrow = mbase + (size_t)i * NN;
            const float* prow = pbase + (size_t)i * NN;
            float sv[8];
            float mx = -1e30f;
#pragma unroll
            for (int t = 0; t < 8; t++) {
                int j = lane + 32 * t;
                float x = __ldg(mrow + j) * (s[r][t] * INV_TEMP + __ldg(prow + j));
                sv[t] = x;
                mx = fmaxf(mx, x);
            }
#pragma unroll
            for (int o = 16; o; o >>= 1) mx = fmaxf(mx, __shfl_xor_sync(0xffffffffu, mx, o));
            float se = 0.f;
#pragma unroll
            for (int t = 0; t < 8; t++) { float e = __expf(sv[t] - mx); sv[t] = e; se += e; }
#pragma unroll
            for (int o = 16; o; o >>= 1) se += __shfl_xor_sync(0xffffffffu, se, o);
            float inv = 1.f / se;
#pragma unroll
            for (int t = 0; t < 8; t++) pb[(w * 8 + r) * NN + lane + 32 * t] = sv[t] * inv;
        }
        __syncwarp();

        float o0[8], o1[8];
#pragma unroll
        for (int r = 0; r < 8; r++) { o0[r] = 0.f; o1[r] = 0.f; }
#pragma unroll 4
        for (int j = 0; j < NN; j++) {
            float2 vv = *reinterpret_cast<const float2*>(&Vs[j * KS_STRIDE + 2 * lane]);
#pragma unroll
            for (int r = 0; r < 8; r++) {
                float pj = pb[(w * 8 + r) * NN + j];
                o0[r] = fmaf(pj, vv.x, o0[r]);
                o1[r] = fmaf(pj, vv.y, o1[r]);
            }
        }
#pragma unroll
        for (int r = 0; r < 8; r++) {
            float2 ov = {o0[r], o1[r]};
            *reinterpret_cast<float2*>(
                g_ao + (size_t)(bp * NN + r0 + r) * CC + h * DD + 2 * lane) = ov;
        }
        __syncwarp();
    }
}

// ---------------- launch ----------------
extern "C" void kernel_launch(void* const* d_in, const int* in_sizes, int n_in,
                              void* d_out, int out_size)
{
    const float* q    = (const float*)d_in[0];
    const float* k    = (const float*)d_in[1];
    const float* v    = (const float*)d_in[2];
    const float* mask = (const float*)d_in[3];
    const float* pos  = (const float*)d_in[4];
    const float* gq   = (const float*)d_in[5];
    const float* bq   = (const float*)d_in[6];
    const float* gk   = (const float*)d_in[7];
    const float* bk   = (const float*)d_in[8];
    const float* gv   = (const float*)d_in[9];
    const float* bv   = (const float*)d_in[10];
    const float* Wq   = (const float*)d_in[11];
    const float* Wk   = (const float*)d_in[12];
    const float* Wv   = (const float*)d_in[13];
    const float* Wo   = (const float*)d_in[14];
    const float* bo   = (const float*)d_in[15];
    float* out = (float*)d_out;

    static bool attr_done = false;
    if (!attr_done) {
        cudaFuncSetAttribute(attn_kernel, cudaFuncAttributeMaxDynamicSharedMemorySize, SMEM_ATTN);
        cudaFuncSetAttribute(mma_gemm_kernel, cudaFuncAttributeMaxDynamicSharedMemorySize, GSMEM);
        attr_done = true;
    }

    // 1. LN + bf16 split of q,k,v
    split_ln_kernel<<<3 * MROWS, 128>>>(q, k, v, gq, bq, gk, bk, gv, bv);

    // 2. split weights
    const int WN4 = CC * CC / 4;
    split_kernel<<<(WN4 + 255) / 256, 256>>>(Wq, 0, WN4);
    split_kernel<<<(WN4 + 255) / 256, 256>>>(Wk, 1, WN4);
    split_kernel<<<(WN4 + 255) / 256, 256>>>(Wv, 2, WN4);
    split_kernel<<<(WN4 + 255) / 256, 256>>>(Wo, 3, WN4);

    // 3. projection GEMMs (tensor core, modes 0..2 via blockIdx.z)
    dim3 gp(CC / 128, MROWS / 128, 3);
    mma_gemm_kernel<<<gp, 256, GSMEM>>>(0, nullptr, nullptr);

    // 4. attention
    attn_kernel<<<dim3(HH, BP), 256, SMEM_ATTN>>>(mask, pos);

    // 5. split attention output, then output GEMM + bias
    const int AN4 = MROWS * CC / 4;
    split_kernel<<<AN4 / 256, 256>>>(nullptr, 4, AN4);
    dim3 go(CC / 128, MROWS / 128, 1);
    mma_gemm_kernel<<<go, 256, GSMEM>>>(3, out, bo);
}

// round 6
// speedup vs baseline: 2.0581x; 1.2226x over previous
#include <cuda_runtime.h>
#include <cuda_bf16.h>
#include <cstdint>

// Problem constants
#define BB 2
#define PP 64
#define NN 256
#define CC 512
#define HH 8
#define DD 64
#define BP (BB*PP)        // 128
#define MROWS (BP*NN)     // 32768
#define INV_TEMP 0.125f
#define LN_EPS 1e-5f

// ---------------- scratch (static device globals; allocation-free) ----------------
// LN'd inputs (A operands of projection GEMMs), hi/lo bf16
__device__ __nv_bfloat16 g_ah[3][(size_t)MROWS * CC];
__device__ __nv_bfloat16 g_al[3][(size_t)MROWS * CC];
// weights hi/lo
__device__ __nv_bfloat16 g_wh[4][(size_t)CC * CC];
__device__ __nv_bfloat16 g_wl[4][(size_t)CC * CC];
// projected q/k/v hi/lo (written by proj GEMM epilogue)
__device__ __nv_bfloat16 g_ph[3][(size_t)MROWS * CC];
__device__ __nv_bfloat16 g_pl[3][(size_t)MROWS * CC];
// attention output hi/lo (A operand of output GEMM)
__device__ __nv_bfloat16 g_aoh[(size_t)MROWS * CC];
__device__ __nv_bfloat16 g_aol[(size_t)MROWS * CC];

// ---------------- helpers ----------------
__device__ __forceinline__ uint32_t s2u(const void* p) {
    uint32_t a;
    asm("{ .reg .u64 t; cvta.to.shared.u64 t, %1; cvt.u32.u64 %0, t; }" : "=r"(a) : "l"(p));
    return a;
}

__device__ __forceinline__ void cp16(uint32_t dst, const void* src) {
    asm volatile("cp.async.cg.shared.global [%0], [%1], 16;" :: "r"(dst), "l"(src) : "memory");
}

__device__ __forceinline__ void ldm4(uint32_t* r, uint32_t addr) {
    asm volatile("ldmatrix.sync.aligned.m8n8.x4.shared.b16 {%0,%1,%2,%3}, [%4];"
                 : "=r"(r[0]), "=r"(r[1]), "=r"(r[2]), "=r"(r[3]) : "r"(addr));
}

__device__ __forceinline__ void ldm4t(uint32_t* r, uint32_t addr) {
    asm volatile("ldmatrix.sync.aligned.m8n8.x4.trans.shared.b16 {%0,%1,%2,%3}, [%4];"
                 : "=r"(r[0]), "=r"(r[1]), "=r"(r[2]), "=r"(r[3]) : "r"(addr));
}

__device__ __forceinline__ void mma16816(float* c, const uint32_t* a, const uint32_t* b) {
    asm volatile(
        "mma.sync.aligned.m16n8k16.row.col.f32.bf16.bf16.f32 "
        "{%0,%1,%2,%3}, {%4,%5,%6,%7}, {%8,%9}, {%0,%1,%2,%3};"
        : "+f"(c[0]), "+f"(c[1]), "+f"(c[2]), "+f"(c[3])
        : "r"(a[0]), "r"(a[1]), "r"(a[2]), "r"(a[3]), "r"(b[0]), "r"(b[1]));
}

__device__ __forceinline__ void split2(float y, __nv_bfloat16& h, __nv_bfloat16& l) {
    h = __float2bfloat16(y);
    l = __float2bfloat16(y - __bfloat162float(h));
}

// pack two floats as (hi0|hi1<<16) and (lo0|lo1<<16) bf16 words
__device__ __forceinline__ void pack_hilo(float v0, float v1, uint32_t& hw, uint32_t& lw) {
    __nv_bfloat16 h0, h1, l0, l1;
    split2(v0, h0, l0); split2(v1, h1, l1);
    hw = (uint32_t)__bfloat16_as_ushort(h0) | ((uint32_t)__bfloat16_as_ushort(h1) << 16);
    lw = (uint32_t)__bfloat16_as_ushort(l0) | ((uint32_t)__bfloat16_as_ushort(l1) << 16);
}

// packed (hi|lo<<16) single-element word
__device__ __forceinline__ uint32_t pack_elem(float p) {
    __nv_bfloat16 h, l;
    split2(p, h, l);
    return (uint32_t)__bfloat16_as_ushort(h) | ((uint32_t)__bfloat16_as_ushort(l) << 16);
}

// ---------------- kernel 1: fused LayerNorm + bf16 hi/lo split for q,k,v ----------------
__global__ __launch_bounds__(128) void split_ln_kernel(
    const float* __restrict__ q, const float* __restrict__ k, const float* __restrict__ v,
    const float* __restrict__ gq, const float* __restrict__ bq,
    const float* __restrict__ gk, const float* __restrict__ bk,
    const float* __restrict__ gv, const float* __restrict__ bv)
{
    int row = blockIdx.x;                       // 0 .. 3*MROWS-1
    int t = (row >= 2 * MROWS) ? 2 : (row >= MROWS ? 1 : 0);
    int r = row - t * MROWS;
    const float* X = (t == 0 ? q : (t == 1 ? k : v)) + (size_t)r * CC;
    const float* G = (t == 0 ? gq : (t == 1 ? gk : gv));
    const float* Bb = (t == 0 ? bq : (t == 1 ? bk : bv));
    __nv_bfloat16* H = g_ah[t] + (size_t)r * CC;
    __nv_bfloat16* L = g_al[t] + (size_t)r * CC;

    int tid = threadIdx.x, lane = tid & 31, wid = tid >> 5;
    float4 u = reinterpret_cast<const float4*>(X)[tid];
    float s = u.x + u.y + u.z + u.w;
    float ss = u.x * u.x + u.y * u.y + u.z * u.z + u.w * u.w;
#pragma unroll
    for (int o = 16; o; o >>= 1) {
        s  += __shfl_xor_sync(0xffffffffu, s, o);
        ss += __shfl_xor_sync(0xffffffffu, ss, o);
    }
    __shared__ float sm1[4], sm2[4];
    if (lane == 0) { sm1[wid] = s; sm2[wid] = ss; }
    __syncthreads();
    s  = sm1[0] + sm1[1] + sm1[2] + sm1[3];
    ss = sm2[0] + sm2[1] + sm2[2] + sm2[3];
    float mu = s * (1.f / CC);
    float rs = rsqrtf(ss * (1.f / CC) - mu * mu + LN_EPS);

    float4 g4 = reinterpret_cast<const float4*>(G)[tid];
    float4 b4 = reinterpret_cast<const float4*>(Bb)[tid];
    float y0 = (u.x - mu) * rs * g4.x + b4.x;
    float y1 = (u.y - mu) * rs * g4.y + b4.y;
    float y2 = (u.z - mu) * rs * g4.z + b4.z;
    float y3 = (u.w - mu) * rs * g4.w + b4.w;

    uint32_t h0, l0, h1, l1;
    pack_hilo(y0, y1, h0, l0);
    pack_hilo(y2, y3, h1, l1);
    reinterpret_cast<uint2*>(H)[tid] = make_uint2(h0, h1);
    reinterpret_cast<uint2*>(L)[tid] = make_uint2(l0, l1);
}

// ---------------- kernel 2: weight fp32 -> bf16 hi/lo split ----------------
__global__ __launch_bounds__(256) void split_kernel(const float* __restrict__ src, int mode, int n4)
{
    __nv_bfloat16* H = g_wh[mode];
    __nv_bfloat16* L = g_wl[mode];
    int i = blockIdx.x * 256 + threadIdx.x;
    if (i >= n4) return;
    float4 u = reinterpret_cast<const float4*>(src)[i];
    uint32_t h0, l0, h1, l1;
    pack_hilo(u.x, u.y, h0, l0);
    pack_hilo(u.z, u.w, h1, l1);
    reinterpret_cast<uint2*>(H)[i] = make_uint2(h0, h1);
    reinterpret_cast<uint2*>(L)[i] = make_uint2(l0, l1);
}

// ---------------- kernel 3: HMMA bf16 GEMM, Y[m][n] = sum_k A[m][k]*W[n][k] (+bias) ----------------
// 3-term split: Ah*Bh + Ah*Bl + Al*Bh, fp32 accumulate.
// CTA 128x128, BK=32; smem tiles 128x32 bf16 (row=64B, 4 chunks of 16B,
// swizzle: chunk ^= (row>>1)&3), double-buffered cp.async.
// Epilogue: modes 0-2 write bf16 hi/lo split to g_ph/g_pl; mode 3 writes fp32+bias.
#define TILE_B 8192
#define STAGE_B 32768
#define GSMEM (2 * STAGE_B)
#define NKI (CC / 32)

__global__ __launch_bounds__(256, 2)
void mma_gemm_kernel(int base_mode, float* __restrict__ out_param, const float* __restrict__ bias_param)
{
    extern __shared__ char smc[];
    const uint32_t sb = s2u(smc);
    const int tid = threadIdx.x, wid = tid >> 5, lane = tid & 31;
    const int warp_m = wid >> 2, warp_n = wid & 3;       // 2 x 4 warps
    const int m0 = blockIdx.y * 128, n0 = blockIdx.x * 128;
    const int mode = base_mode + blockIdx.z;

    const __nv_bfloat16 *Ah, *Al;
    if (mode < 3) { Ah = g_ah[mode]; Al = g_al[mode]; }
    else          { Ah = g_aoh;      Al = g_aol; }
    const __nv_bfloat16* Bh = g_wh[mode];
    const __nv_bfloat16* Bl = g_wl[mode];

    float acc[4][4][4];
#pragma unroll
    for (int i = 0; i < 4; i++)
#pragma unroll
        for (int j = 0; j < 4; j++)
#pragma unroll
            for (int x = 0; x < 4; x++) acc[i][j][x] = 0.f;

    const int lrow = tid >> 1;          // 0..127
    const int lc0  = (tid & 1) * 2;     // chunk 0 or 2

    auto issue_loads = [&](int s, int k0) {
        uint32_t sst = sb + s * STAGE_B;
        const size_t ga = (size_t)(m0 + lrow) * CC + k0;
        const size_t gb = (size_t)(n0 + lrow) * CC + k0;
#pragma unroll
        for (int i = 0; i < 2; i++) {
            int c = lc0 + i;
            uint32_t d = (uint32_t)(lrow * 64 + ((c ^ ((lrow >> 1) & 3)) * 16));
            cp16(sst + 0 * TILE_B + d, Ah + ga + c * 8);
            cp16(sst + 1 * TILE_B + d, Al + ga + c * 8);
            cp16(sst + 2 * TILE_B + d, Bh + gb + c * 8);
            cp16(sst + 3 * TILE_B + d, Bl + gb + c * 8);
        }
    };

    issue_loads(0, 0);
    asm volatile("cp.async.commit_group;" ::: "memory");

    for (int it = 0; it < NKI; it++) {
        if (it + 1 < NKI) {
            issue_loads((it + 1) & 1, (it + 1) * 32);
            asm volatile("cp.async.commit_group;" ::: "memory");
            asm volatile("cp.async.wait_group 1;" ::: "memory");
        } else {
            asm volatile("cp.async.wait_group 0;" ::: "memory");
        }
        __syncthreads();

        const uint32_t st = sb + (it & 1) * STAGE_B;
#pragma unroll
        for (int kk = 0; kk < 2; kk++) {
            uint32_t af[4][4], bf[2][4];
            int ar = warp_m * 64 + (lane & 7) + ((lane >> 3) & 1) * 8;
            int ac = kk * 2 + ((lane >> 4) & 1);
            int br = warp_n * 32 + (lane & 7) + ((lane >> 4) & 1) * 8;
            int bc = kk * 2 + ((lane >> 3) & 1);

#pragma unroll
            for (int np = 0; np < 2; np++) {
                int r = br + np * 16;
                ldm4(bf[np], st + 2 * TILE_B + r * 64 + ((bc ^ ((r >> 1) & 3)) * 16));
            }
#pragma unroll
            for (int mt = 0; mt < 4; mt++) {
                int r = ar + mt * 16;
                ldm4(af[mt], st + 0 * TILE_B + r * 64 + ((ac ^ ((r >> 1) & 3)) * 16));
            }
#pragma unroll
            for (int mt = 0; mt < 4; mt++)
#pragma unroll
                for (int nt = 0; nt < 4; nt++)
                    mma16816(acc[mt][nt], af[mt], &bf[nt >> 1][(nt & 1) * 2]);

#pragma unroll
            for (int np = 0; np < 2; np++) {
                int r = br + np * 16;
                ldm4(bf[np], st + 3 * TILE_B + r * 64 + ((bc ^ ((r >> 1) & 3)) * 16));
            }
#pragma unroll
            for (int mt = 0; mt < 4; mt++)
#pragma unroll
                for (int nt = 0; nt < 4; nt++)
                    mma16816(acc[mt][nt], af[mt], &bf[nt >> 1][(nt & 1) * 2]);

#pragma unroll
            for (int mt = 0; mt < 4; mt++) {
                int r = ar + mt * 16;
                ldm4(af[mt], st + 1 * TILE_B + r * 64 + ((ac ^ ((r >> 1) & 3)) * 16));
            }
#pragma unroll
            for (int np = 0; np < 2; np++) {
                int r = br + np * 16;
                ldm4(bf[np], st + 2 * TILE_B + r * 64 + ((bc ^ ((r >> 1) & 3)) * 16));
            }
#pragma unroll
            for (int mt = 0; mt < 4; mt++)
#pragma unroll
                for (int nt = 0; nt < 4; nt++)
                    mma16816(acc[mt][nt], af[mt], &bf[nt >> 1][(nt & 1) * 2]);
        }
        __syncthreads();
    }

    // epilogue
    if (mode < 3) {
        __nv_bfloat16* H = g_ph[mode];
        __nv_bfloat16* L = g_pl[mode];
#pragma unroll
        for (int mt = 0; mt < 4; mt++) {
#pragma unroll
            for (int nt = 0; nt < 4; nt++) {
                int r = m0 + warp_m * 64 + mt * 16 + (lane >> 2);
                int col = n0 + warp_n * 32 + nt * 8 + (lane & 3) * 2;
                uint32_t hw, lw;
                pack_hilo(acc[mt][nt][0], acc[mt][nt][1], hw, lw);
                *reinterpret_cast<uint32_t*>(H + (size_t)r * CC + col) = hw;
                *reinterpret_cast<uint32_t*>(L + (size_t)r * CC + col) = lw;
                pack_hilo(acc[mt][nt][2], acc[mt][nt][3], hw, lw);
                *reinterpret_cast<uint32_t*>(H + (size_t)(r + 8) * CC + col) = hw;
                *reinterpret_cast<uint32_t*>(L + (size_t)(r + 8) * CC + col) = lw;
            }
        }
    } else {
        float* O = out_param;
        const float* bias = bias_param;
#pragma unroll
        for (int mt = 0; mt < 4; mt++) {
#pragma unroll
            for (int nt = 0; nt < 4; nt++) {
                int r = m0 + warp_m * 64 + mt * 16 + (lane >> 2);
                int col = n0 + warp_n * 32 + nt * 8 + (lane & 3) * 2;
                float b0 = bias[col], b1 = bias[col + 1];
                float2 v0 = {acc[mt][nt][0] + b0, acc[mt][nt][1] + b1};
                float2 v1 = {acc[mt][nt][2] + b0, acc[mt][nt][3] + b1};
                *reinterpret_cast<float2*>(O + (size_t)r * CC + col) = v0;
                *reinterpret_cast<float2*>(O + (size_t)(r + 8) * CC + col) = v1;
            }
        }
    }
}

// ---------------- kernel 4: tensor-core windowed masked attention ----------------
// block = (h, bp). K/V hi/lo resident in smem; 4 iterations over 64 query rows.
// S = 3-term bf16 MMA; softmax in regs via swizzled fp32 smem buffer; P stored
// packed (hi|lo) in place; PV = 3-term MMA with LDS.64+PRMT A-frags and
// ldmatrix.trans V-frags. Output written as bf16 hi/lo split for the Wo GEMM.
#define AKH 0
#define AKL 32768
#define AVH 65536
#define AVL 98304
#define AQH 131072
#define AQL 139264
#define ASP 147456
#define ASMEM (ASP + 65536)   // 212992 bytes

__global__ __launch_bounds__(256, 1) void attn_tc_kernel(
    const float* __restrict__ mask, const float* __restrict__ pos)
{
    extern __shared__ char smc[];
    const uint32_t sb = s2u(smc);
    const int h = blockIdx.x, bp = blockIdx.y;
    const int tid = threadIdx.x, wid = tid >> 5, lane = tid & 31;
    const int warp_m = wid >> 1, warp_n = wid & 1;    // 4 x 2 warps

    // ---- fill K/V hi/lo tiles (256 rows x 64 bf16 = 128B rows, SW128 swizzle) ----
    for (int i = tid; i < 2048; i += 256) {
        int row = i >> 3, c = i & 7;
        uint32_t d = (uint32_t)(row * 128 + ((c ^ (row & 7)) << 4));
        size_t g = (size_t)(bp * NN + row) * CC + h * DD + c * 8;
        cp16(sb + AKH + d, g_ph[1] + g);
        cp16(sb + AKL + d, g_pl[1] + g);
        cp16(sb + AVH + d, g_ph[2] + g);
        cp16(sb + AVL + d, g_pl[2] + g);
    }
    asm volatile("cp.async.commit_group;" ::: "memory");

    const size_t mbase = (size_t)bp * NN * NN;
    const size_t pbase = (size_t)h * NN * NN;

    for (int it = 0; it < 4; it++) {
        // ---- load Q tile (64 rows) hi/lo ----
        for (int i = tid; i < 512; i += 256) {
            int row = i >> 3, c = i & 7;
            uint32_t d = (uint32_t)(row * 128 + ((c ^ (row & 7)) << 4));
            size_t g = (size_t)(bp * NN + it * 64 + row) * CC + h * DD + c * 8;
            cp16(sb + AQH + d, g_ph[0] + g);
            cp16(sb + AQL + d, g_pl[0] + g);
        }
        asm volatile("cp.async.commit_group;" ::: "memory");
        asm volatile("cp.async.wait_group 0;" ::: "memory");
        __syncthreads();   // Q ready; also separates prior iter's PV reads from S writes

        // ---- S = Q K^T (warp: 16 rows x 128 cols, k=64) ----
        float cS[16][4];
#pragma unroll
        for (int i = 0; i < 16; i++)
#pragma unroll
            for (int x = 0; x < 4; x++) cS[i][x] = 0.f;

#pragma unroll
        for (int ks = 0; ks < 4; ks++) {
            uint32_t ah[4], al[4];
            {
                int ar = warp_m * 16 + (lane & 7) + ((lane >> 3) & 1) * 8;
                int ac = ks * 2 + ((lane >> 4) & 1);
                uint32_t ad = sb + AQH + ar * 128 + (((ac ^ (ar & 7)) & 7) << 4);
                ldm4(ah, ad);
                ldm4(al, ad + (AQL - AQH));
            }
#pragma unroll
            for (int nt2 = 0; nt2 < 8; nt2++) {
                int br = warp_n * 128 + nt2 * 16 + (lane & 7) + ((lane >> 4) & 1) * 8;
                int bc = ks * 2 + ((lane >> 3) & 1);
                uint32_t bd = sb + AKH + br * 128 + (((bc ^ (br & 7)) & 7) << 4);
                uint32_t bh[4], bl[4];
                ldm4(bh, bd);
                ldm4(bl, bd + (AKL - AKH));
                mma16816(cS[2 * nt2],     ah, bh);
                mma16816(cS[2 * nt2 + 1], ah, bh + 2);
                mma16816(cS[2 * nt2],     al, bh);
                mma16816(cS[2 * nt2 + 1], al, bh + 2);
                mma16816(cS[2 * nt2],     ah, bl);
                mma16816(cS[2 * nt2 + 1], ah, bl + 2);
            }
        }

        // ---- x = mask*(s*INV_TEMP + pos); store fp32 to swizzled S buffer ----
        {
            const int i0 = warp_m * 16 + (lane >> 2);
            const size_t mr0 = mbase + (size_t)(it * 64 + i0) * NN;
            const size_t pr0 = pbase + (size_t)(it * 64 + i0) * NN;
#pragma unroll
            for (int nt = 0; nt < 16; nt++) {
                int j = warp_n * 128 + nt * 8 + 2 * (lane & 3);
                float2 m0 = __ldg(reinterpret_cast<const float2*>(mask + mr0 + j));
                float2 p0 = __ldg(reinterpret_cast<const float2*>(pos  + pr0 + j));
                float2 m1 = __ldg(reinterpret_cast<const float2*>(mask + mr0 + 8 * NN + j));
                float2 p1 = __ldg(reinterpret_cast<const float2*>(pos  + pr0 + 8 * NN + j));
                float x0 = m0.x * (cS[nt][0] * INV_TEMP + p0.x);
                float x1 = m0.y * (cS[nt][1] * INV_TEMP + p0.y);
                float x2 = m1.x * (cS[nt][2] * INV_TEMP + p1.x);
                float x3 = m1.y * (cS[nt][3] * INV_TEMP + p1.y);
                int ch = j >> 3;
                int r0 = i0, r1 = i0 + 8;
                uint32_t a0 = ASP + r0 * 1024 + ((uint32_t)((ch & ~7) | ((ch & 7) ^ (r0 & 7))) << 5) + (j & 7) * 4;
                uint32_t a1 = ASP + r1 * 1024 + ((uint32_t)((ch & ~7) | ((ch & 7) ^ (r1 & 7))) << 5) + (j & 7) * 4;
                *reinterpret_cast<float2*>(smc + a0) = make_float2(x0, x1);
                *reinterpret_cast<float2*>(smc + a1) = make_float2(x2, x3);
            }
        }
        __syncthreads();

        // ---- softmax per row; write packed (hi|lo) bf16 P in place ----
#pragma unroll
        for (int rr = 0; rr < 8; rr++) {
            int r = wid * 8 + rr;
            uint32_t ad = ASP + r * 1024 + ((uint32_t)((lane & ~7) | ((lane & 7) ^ (r & 7))) << 5);
            float4 v0 = *reinterpret_cast<float4*>(smc + ad);
            float4 v1 = *reinterpret_cast<float4*>(smc + ad + 16);
            float mx = fmaxf(fmaxf(fmaxf(v0.x, v0.y), fmaxf(v0.z, v0.w)),
                             fmaxf(fmaxf(v1.x, v1.y), fmaxf(v1.z, v1.w)));
#pragma unroll
            for (int o = 16; o; o >>= 1) mx = fmaxf(mx, __shfl_xor_sync(0xffffffffu, mx, o));
            float e[8];
            e[0] = __expf(v0.x - mx); e[1] = __expf(v0.y - mx);
            e[2] = __expf(v0.z - mx); e[3] = __expf(v0.w - mx);
            e[4] = __expf(v1.x - mx); e[5] = __expf(v1.y - mx);
            e[6] = __expf(v1.z - mx); e[7] = __expf(v1.w - mx);
            float se = e[0] + e[1] + e[2] + e[3] + e[4] + e[5] + e[6] + e[7];
#pragma unroll
            for (int o = 16; o; o >>= 1) se += __shfl_xor_sync(0xffffffffu, se, o);
            float inv = 1.f / se;
            uint4 w0, w1;
            w0.x = pack_elem(e[0] * inv); w0.y = pack_elem(e[1] * inv);
            w0.z = pack_elem(e[2] * inv); w0.w = pack_elem(e[3] * inv);
            w1.x = pack_elem(e[4] * inv); w1.y = pack_elem(e[5] * inv);
            w1.z = pack_elem(e[6] * inv); w1.w = pack_elem(e[7] * inv);
            *reinterpret_cast<uint4*>(smc + ad) = w0;
            *reinterpret_cast<uint4*>(smc + ad + 16) = w1;
        }
        __syncthreads();

        // ---- O = P V (warp: 16 rows x 32 cols, k=256) ----
        float o[4][4];
#pragma unroll
        for (int i = 0; i < 4; i++)
#pragma unroll
            for (int x = 0; x < 4; x++) o[i][x] = 0.f;

#pragma unroll
        for (int ks = 0; ks < 16; ks++) {
            uint32_t ah[4], al[4];
            const int r0 = warp_m * 16 + (lane >> 2);
            const int cb = (lane & 3) * 8;
#pragma unroll
            for (int half = 0; half < 2; half++) {
                int ch = 2 * ks + half;
#pragma unroll
                for (int rh = 0; rh < 2; rh++) {
                    int r = r0 + rh * 8;
                    uint32_t ad = ASP + r * 1024 +
                        ((uint32_t)((ch & ~7) | ((ch & 7) ^ (r & 7))) << 5) + cb;
                    uint2 w = *reinterpret_cast<uint2*>(smc + ad);
                    ah[half * 2 + rh] = __byte_perm(w.x, w.y, 0x5410);
                    al[half * 2 + rh] = __byte_perm(w.x, w.y, 0x7632);
                }
            }
#pragma unroll
            for (int nt16 = 0; nt16 < 2; nt16++) {
                int vr = ks * 16 + (lane & 7) + ((lane >> 3) & 1) * 8;
                int vc = warp_n * 4 + nt16 * 2 + ((lane >> 4) & 1);
                uint32_t vd = sb + AVH + vr * 128 + (((vc ^ (vr & 7)) & 7) << 4);
                uint32_t bh[4], bl[4];
                ldm4t(bh, vd);
                ldm4t(bl, vd + (AVL - AVH));
                mma16816(o[nt16 * 2],     ah, bh);
                mma16816(o[nt16 * 2 + 1], ah, bh + 2);
                mma16816(o[nt16 * 2],     al, bh);
                mma16816(o[nt16 * 2 + 1], al, bh + 2);
                mma16816(o[nt16 * 2],     ah, bl);
                mma16816(o[nt16 * 2 + 1], ah, bl + 2);
            }
        }

        // ---- epilogue: write bf16 hi/lo split attention output ----
#pragma unroll
        for (int nt = 0; nt < 4; nt++) {
            int rl = warp_m * 16 + (lane >> 2);
            int dl = warp_n * 32 + nt * 8 + 2 * (lane & 3);
            size_t g0 = (size_t)(bp * NN + it * 64 + rl) * CC + h * DD + dl;
            size_t g1 = g0 + 8 * CC;
            uint32_t hw, lw;
            pack_hilo(o[nt][0], o[nt][1], hw, lw);
            *reinterpret_cast<uint32_t*>(g_aoh + g0) = hw;
            *reinterpret_cast<uint32_t*>(g_aol + g0) = lw;
            pack_hilo(o[nt][2], o[nt][3], hw, lw);
            *reinterpret_cast<uint32_t*>(g_aoh + g1) = hw;
            *reinterpret_cast<uint32_t*>(g_aol + g1) = lw;
        }
    }
}

// ---------------- launch ----------------
extern "C" void kernel_launch(void* const* d_in, const int* in_sizes, int n_in,
                              void* d_out, int out_size)
{
    const float* q    = (const float*)d_in[0];
    const float* k    = (const float*)d_in[1];
    const float* v    = (const float*)d_in[2];
    const float* mask = (const float*)d_in[3];
    const float* pos  = (const float*)d_in[4];
    const float* gq   = (const float*)d_in[5];
    const float* bq   = (const float*)d_in[6];
    const float* gk   = (const float*)d_in[7];
    const float* bk   = (const float*)d_in[8];
    const float* gv   = (const float*)d_in[9];
    const float* bv   = (const float*)d_in[10];
    const float* Wq   = (const float*)d_in[11];
    const float* Wk   = (const float*)d_in[12];
    const float* Wv   = (const float*)d_in[13];
    const float* Wo   = (const float*)d_in[14];
    const float* bo   = (const float*)d_in[15];
    float* out = (float*)d_out;

    static bool attr_done = false;
    if (!attr_done) {
        cudaFuncSetAttribute(attn_tc_kernel, cudaFuncAttributeMaxDynamicSharedMemorySize, ASMEM);
        cudaFuncSetAttribute(mma_gemm_kernel, cudaFuncAttributeMaxDynamicSharedMemorySize, GSMEM);
        attr_done = true;
    }

    // 1. LN + bf16 split of q,k,v
    split_ln_kernel<<<3 * MROWS, 128>>>(q, k, v, gq, bq, gk, bk, gv, bv);

    // 2. split weights
    const int WN4 = CC * CC / 4;
    split_kernel<<<(WN4 + 255) / 256, 256>>>(Wq, 0, WN4);
    split_kernel<<<(WN4 + 255) / 256, 256>>>(Wk, 1, WN4);
    split_kernel<<<(WN4 + 255) / 256, 256>>>(Wv, 2, WN4);
    split_kernel<<<(WN4 + 255) / 256, 256>>>(Wo, 3, WN4);

    // 3. projection GEMMs (modes 0..2 via blockIdx.z), split epilogue
    dim3 gp(CC / 128, MROWS / 128, 3);
    mma_gemm_kernel<<<gp, 256, GSMEM>>>(0, nullptr, nullptr);

    // 4. tensor-core attention (writes split output directly)
    attn_tc_kernel<<<dim3(HH, BP), 256, ASMEM>>>(mask, pos);

    // 5. output GEMM + bias
    dim3 go(CC / 128, MROWS / 128, 1);
    mma_gemm_kernel<<<go, 256, GSMEM>>>(3, out, bo);
}